// round 5
// baseline (speedup 1.0000x reference)
#include <cuda_runtime.h>
#include <cstdint>

#define D_MODEL 1024
#define N_LAYER 2
#define VOCAB   50264
#define D_STATE 16
#define D_INNER 2048
#define DT_RANK 64
#define SEQ_L   2048

// ---------------- scratch (static device globals; no allocations) ----------------
__device__ float g_x   [SEQ_L * D_MODEL];        // residual stream
__device__ float g_xn  [SEQ_L * D_MODEL];        // normed
__device__ float g_xr  [SEQ_L * 2 * D_INNER];    // x_and_res (in_proj out)
__device__ float g_xp  [SEQ_L * D_INNER];        // conv+silu out (u)
__device__ float g_xdbl[SEQ_L * 96];             // [delta_raw(64) | B(16) | C(16)]
__device__ float g_dt  [SEQ_L * D_INNER];        // softplus(delta)
__device__ float g_y   [SEQ_L * D_INNER];        // scan out (gated)

// ---------------- embedding gather ----------------
__global__ void embed_kernel(const int* __restrict__ ids,
                             const float* __restrict__ emb,
                             float* __restrict__ x)
{
    int t = blockIdx.x;
    int id = ids[t];
    const float4* e = (const float4*)(emb + (long)id * D_MODEL);
    float4* o = (float4*)(x + (long)t * D_MODEL);
    o[threadIdx.x] = e[threadIdx.x];
}

// ---------------- rmsnorm: one block per row, 256 threads x float4 ----------------
__global__ void rmsnorm_kernel(const float* __restrict__ x,
                               const float* __restrict__ w,
                               float* __restrict__ out)
{
    __shared__ float red[8];
    int t = blockIdx.x;
    float4 v = ((const float4*)(x + (long)t * D_MODEL))[threadIdx.x];
    float s = v.x*v.x + v.y*v.y + v.z*v.z + v.w*v.w;
    #pragma unroll
    for (int off = 16; off; off >>= 1) s += __shfl_xor_sync(0xffffffffu, s, off);
    if ((threadIdx.x & 31) == 0) red[threadIdx.x >> 5] = s;
    __syncthreads();
    float tot = red[0]+red[1]+red[2]+red[3]+red[4]+red[5]+red[6]+red[7];
    float scale = rsqrtf(tot * (1.0f / (float)D_MODEL) + 1e-5f);
    float4 wv = ((const float4*)w)[threadIdx.x];
    float4 o;
    o.x = v.x * scale * wv.x;
    o.y = v.y * scale * wv.y;
    o.z = v.z * scale * wv.z;
    o.w = v.w * scale * wv.w;
    ((float4*)(out + (long)t * D_MODEL))[threadIdx.x] = o;
}

// ---------------- general NT GEMM: C[M,N] = A[M,K] * B[N,K]^T (f32x2 FFMA2) ----
// EPI: 0 = store, 1 = C += acc (residual in-place), 2 = softplus(acc + bias[n])
union F2U { unsigned long long u; float f[2]; };
union F4U { float4 f4; unsigned long long u[2]; };

template<int EPI>
__global__ __launch_bounds__(256)
void gemm_nt(const float* __restrict__ A, int lda,
             const float* __restrict__ B, int ldb,
             float* __restrict__ C, int ldc,
             const float* __restrict__ X,
             int M, int N, int K)
{
    __shared__ float As[16][132];
    __shared__ float Bs[16][132];
    const int tid = threadIdx.x;
    const int bm = blockIdx.y * 128;
    const int bn = blockIdx.x * 128;
    const int m0 = (tid >> 4) * 8;
    const int n0 = (tid & 15) * 8;

    F2U acc[8][4];
    #pragma unroll
    for (int i = 0; i < 8; i++)
        #pragma unroll
        for (int j = 0; j < 4; j++) acc[i][j].u = 0ull;

    for (int kt = 0; kt < K; kt += 16) {
        #pragma unroll
        for (int s = 0; s < 2; s++) {
            int id  = tid + s * 256;
            int row = id >> 2;
            int k0  = (id & 3) << 2;
            float4 av = make_float4(0.f, 0.f, 0.f, 0.f);
            float4 bv = av;
            int ar = bm + row;
            int br = bn + row;
            if (ar < M) av = *(const float4*)(A + (long)ar * lda + kt + k0);
            if (br < N) bv = *(const float4*)(B + (long)br * ldb + kt + k0);
            As[k0+0][row] = av.x; As[k0+1][row] = av.y;
            As[k0+2][row] = av.z; As[k0+3][row] = av.w;
            Bs[k0+0][row] = bv.x; Bs[k0+1][row] = bv.y;
            Bs[k0+2][row] = bv.z; Bs[k0+3][row] = bv.w;
        }
        __syncthreads();
        #pragma unroll
        for (int k = 0; k < 16; k++) {
            float4 a0 = *(const float4*)&As[k][m0];
            float4 a1 = *(const float4*)&As[k][m0 + 4];
            F4U b0, b1;
            b0.f4 = *(const float4*)&Bs[k][n0];
            b1.f4 = *(const float4*)&Bs[k][n0 + 4];
            unsigned long long bb[4] = { b0.u[0], b0.u[1], b1.u[0], b1.u[1] };
            float av[8] = { a0.x, a0.y, a0.z, a0.w, a1.x, a1.y, a1.z, a1.w };
            #pragma unroll
            for (int i = 0; i < 8; i++) {
                unsigned long long ap;
                unsigned int ai = __float_as_uint(av[i]);
                asm("mov.b64 %0, {%1, %1};" : "=l"(ap) : "r"(ai));
                #pragma unroll
                for (int j = 0; j < 4; j++) {
                    asm("fma.rn.f32x2 %0, %1, %2, %0;"
                        : "+l"(acc[i][j].u) : "l"(ap), "l"(bb[j]));
                }
            }
        }
        __syncthreads();
    }

    #pragma unroll
    for (int i = 0; i < 8; i++) {
        int gm = bm + m0 + i;
        if (gm >= M) continue;
        #pragma unroll
        for (int j = 0; j < 4; j++) {
            #pragma unroll
            for (int h = 0; h < 2; h++) {
                int gn = bn + n0 + j * 2 + h;
                if (gn >= N) continue;
                float v = acc[i][j].f[h];
                long off = (long)gm * ldc + gn;
                if (EPI == 0) {
                    C[off] = v;
                } else if (EPI == 1) {
                    C[off] = C[off] + v;
                } else {
                    float z = v + X[gn];
                    C[off] = (z > 20.f) ? z : log1pf(__expf(z));
                }
            }
        }
    }
}

// ---------------- causal depthwise conv(4) + silu ----------------
__global__ void conv_silu_kernel(const float* __restrict__ xr,
                                 const float* __restrict__ w,
                                 const float* __restrict__ b,
                                 float* __restrict__ xp)
{
    int idx = blockIdx.x * 256 + threadIdx.x;   // idx = t*D_INNER + c
    int c = idx & (D_INNER - 1);
    int t = idx >> 11;
    float w0 = w[c*4+0], w1 = w[c*4+1], w2 = w[c*4+2], w3 = w[c*4+3];
    float acc = b[c];
    const float* col = xr + c;
    const int stride = 2 * D_INNER;
    if (t >= 3) acc += w0 * col[(long)(t-3) * stride];
    if (t >= 2) acc += w1 * col[(long)(t-2) * stride];
    if (t >= 1) acc += w2 * col[(long)(t-1) * stride];
    acc += w3 * col[(long)t * stride];
    xp[idx] = acc / (1.f + __expf(-acc));
}

// ---------------- skinny x_proj: xdbl[t,96] = xp[t,:] @ W[96,2048]^T -----------
__global__ __launch_bounds__(256)
void xproj_kernel(const float* __restrict__ xp, const float* __restrict__ W,
                  float* __restrict__ xdbl)
{
    __shared__ float srow[4][D_INNER];
    int t0 = blockIdx.x * 4;
    const float4* src = (const float4*)(xp + (long)t0 * D_INNER);
    float4* dst = (float4*)&srow[0][0];
    for (int i = threadIdx.x; i < 4 * D_INNER / 4; i += 256) dst[i] = src[i];
    __syncthreads();
    int warp = threadIdx.x >> 5, lane = threadIdx.x & 31;
    for (int col = warp; col < 96; col += 8) {
        const float4* w4 = (const float4*)(W + (long)col * D_INNER);
        const float4* s0 = (const float4*)srow[0];
        const float4* s1 = (const float4*)srow[1];
        const float4* s2 = (const float4*)srow[2];
        const float4* s3 = (const float4*)srow[3];
        float a0 = 0.f, a1 = 0.f, a2 = 0.f, a3 = 0.f;
        #pragma unroll 4
        for (int i = lane; i < D_INNER / 4; i += 32) {
            float4 wv = w4[i];
            float4 x0 = s0[i], x1 = s1[i], x2 = s2[i], x3 = s3[i];
            a0 += x0.x*wv.x + x0.y*wv.y + x0.z*wv.z + x0.w*wv.w;
            a1 += x1.x*wv.x + x1.y*wv.y + x1.z*wv.z + x1.w*wv.w;
            a2 += x2.x*wv.x + x2.y*wv.y + x2.z*wv.z + x2.w*wv.w;
            a3 += x3.x*wv.x + x3.y*wv.y + x3.z*wv.z + x3.w*wv.w;
        }
        #pragma unroll
        for (int off = 16; off; off >>= 1) {
            a0 += __shfl_xor_sync(0xffffffffu, a0, off);
            a1 += __shfl_xor_sync(0xffffffffu, a1, off);
            a2 += __shfl_xor_sync(0xffffffffu, a2, off);
            a3 += __shfl_xor_sync(0xffffffffu, a3, off);
        }
        if (lane == 0) {
            xdbl[(long)(t0+0)*96 + col] = a0;
            xdbl[(long)(t0+1)*96 + col] = a1;
            xdbl[(long)(t0+2)*96 + col] = a2;
            xdbl[(long)(t0+3)*96 + col] = a3;
        }
    }
}

// ---------------- selective scan: thread per (d, n), 16-lane reduce ----------
// y[t,d] = (sum_n h[t,d,n]*C[t,n] + u[t,d]*D[d]) * silu(res[t,d])
__global__ __launch_bounds__(128)
void scan_kernel(const float* __restrict__ delta, const float* __restrict__ u,
                 const float* __restrict__ xdbl,  const float* __restrict__ A_log,
                 const float* __restrict__ Dp,    const float* __restrict__ xr,
                 float* __restrict__ y)
{
    int tid = threadIdx.x;
    int n = tid & 15;
    int d = blockIdx.x * (blockDim.x >> 4) + (tid >> 4);
    float A  = -__expf(A_log[d * D_STATE + n]);
    float Dv = Dp[d];
    float h = 0.f;
    const float* dptr = delta + d;
    const float* uptr = u + d;
    const float* bptr = xdbl + 64 + n;
    const float* cptr = xdbl + 80 + n;
    const float* rptr = xr + D_INNER + d;
    #pragma unroll 4
    for (int t = 0; t < SEQ_L; t++) {
        float dt = dptr[(long)t * D_INNER];
        float uu = uptr[(long)t * D_INNER];
        float bb = bptr[(long)t * 96];
        float cc = cptr[(long)t * 96];
        float dA = __expf(dt * A);
        h = dA * h + (dt * uu) * bb;
        float p = h * cc;
        p += __shfl_xor_sync(0xffffffffu, p, 8);
        p += __shfl_xor_sync(0xffffffffu, p, 4);
        p += __shfl_xor_sync(0xffffffffu, p, 2);
        p += __shfl_xor_sync(0xffffffffu, p, 1);
        if (n == 0) {
            float r = rptr[(long)t * (2 * D_INNER)];
            float g = r / (1.f + __expf(-r));
            y[(long)t * D_INNER + d] = (p + uu * Dv) * g;
        }
    }
}

// ---------------- driver ----------------
extern "C" void kernel_launch(void* const* d_in, const int* in_sizes, int n_in,
                              void* d_out, int out_size)
{
    const int*   ids    = (const int*)  d_in[0];
    const float* emb    = (const float*)d_in[1];
    const float* inpw   = (const float*)d_in[2];
    const float* convw  = (const float*)d_in[3];
    const float* convb  = (const float*)d_in[4];
    const float* xprojw = (const float*)d_in[5];
    const float* dtw    = (const float*)d_in[6];
    const float* dtb    = (const float*)d_in[7];
    const float* alog   = (const float*)d_in[8];
    const float* dpar   = (const float*)d_in[9];
    const float* outw   = (const float*)d_in[10];
    const float* normw  = (const float*)d_in[11];
    const float* normf  = (const float*)d_in[12];
    float* logits = (float*)d_out;

    float *x, *xn, *xr, *xp, *xdbl, *dt, *y;
    cudaGetSymbolAddress((void**)&x,    g_x);
    cudaGetSymbolAddress((void**)&xn,   g_xn);
    cudaGetSymbolAddress((void**)&xr,   g_xr);
    cudaGetSymbolAddress((void**)&xp,   g_xp);
    cudaGetSymbolAddress((void**)&xdbl, g_xdbl);
    cudaGetSymbolAddress((void**)&dt,   g_dt);
    cudaGetSymbolAddress((void**)&y,    g_y);

    embed_kernel<<<SEQ_L, 256>>>(ids, emb, x);

    for (int i = 0; i < N_LAYER; i++) {
        const float* w_in   = inpw   + (long)i * (2 * D_INNER) * D_MODEL;
        const float* w_conv = convw  + (long)i * D_INNER * 4;
        const float* b_conv = convb  + (long)i * D_INNER;
        const float* w_xprj = xprojw + (long)i * 96 * D_INNER;
        const float* w_dt   = dtw    + (long)i * D_INNER * DT_RANK;
        const float* b_dt   = dtb    + (long)i * D_INNER;
        const float* a_log  = alog   + (long)i * D_INNER * D_STATE;
        const float* d_prm  = dpar   + (long)i * D_INNER;
        const float* w_out  = outw   + (long)i * D_MODEL * D_INNER;
        const float* w_nrm  = normw  + (long)i * D_MODEL;

        rmsnorm_kernel<<<SEQ_L, 256>>>(x, w_nrm, xn);

        // x_and_res = xn @ in_proj^T : M=2048, N=4096, K=1024
        gemm_nt<0><<<dim3((2*D_INNER)/128, SEQ_L/128), 256>>>(
            xn, D_MODEL, w_in, D_MODEL, xr, 2*D_INNER, nullptr,
            SEQ_L, 2*D_INNER, D_MODEL);

        conv_silu_kernel<<<(SEQ_L * D_INNER) / 256, 256>>>(xr, w_conv, b_conv, xp);

        // x_dbl = xp @ x_proj^T : M=2048, N=96, K=2048
        xproj_kernel<<<SEQ_L / 4, 256>>>(xp, w_xprj, xdbl);

        // delta = softplus(x_dbl[:, :64] @ dt_proj^T + b) : M=2048, N=2048, K=64
        gemm_nt<2><<<dim3(D_INNER/128, SEQ_L/128), 256>>>(
            xdbl, 96, w_dt, DT_RANK, dt, D_INNER, b_dt,
            SEQ_L, D_INNER, DT_RANK);

        scan_kernel<<<D_INNER / 8, 128>>>(dt, xp, xdbl, a_log, d_prm, xr, y);

        // x += y @ out_proj^T : M=2048, N=1024, K=2048 (residual epilogue)
        gemm_nt<1><<<dim3(D_MODEL/128, SEQ_L/128), 256>>>(
            y, D_INNER, w_out, D_INNER, x, D_MODEL, nullptr,
            SEQ_L, D_MODEL, D_INNER);
    }

    rmsnorm_kernel<<<SEQ_L, 256>>>(x, normf, xn);

    // logits = xn @ embedding^T : M=2048, N=50264, K=1024
    gemm_nt<0><<<dim3((VOCAB + 127) / 128, SEQ_L / 128), 256>>>(
        xn, D_MODEL, emb, D_MODEL, logits, VOCAB, nullptr,
        SEQ_L, VOCAB, D_MODEL);
}

// round 7
// speedup vs baseline: 1.7091x; 1.7091x over previous
#include <cuda_runtime.h>
#include <cuda_bf16.h>
#include <cstdint>

#define D_MODEL 1024
#define N_LAYER 2
#define VOCAB   50264
#define D_STATE 16
#define D_INNER 2048
#define DT_RANK 64
#define SEQ_L   2048

// ======================= helpers =======================
__device__ __forceinline__ uint32_t smem_u32(const void* p) {
    uint32_t a;
    asm("{ .reg .u64 t; cvta.to.shared.u64 t, %1; cvt.u32.u64 %0, t; }" : "=r"(a) : "l"(p));
    return a;
}
#define SWZ128(b) ((b) ^ (((b) >> 3) & 0x70))

#define CP_ASYNC16(saddr, gaddr) \
    asm volatile("cp.async.cg.shared.global [%0], [%1], 16;" :: "r"(saddr), "l"(gaddr) : "memory")
#define CP_ASYNC16_Z(saddr, gaddr, sz) \
    asm volatile("cp.async.cg.shared.global [%0], [%1], 16, %2;" :: "r"(saddr), "l"(gaddr), "r"(sz) : "memory")
#define CP_COMMIT()  asm volatile("cp.async.commit_group;" ::: "memory")
#define CP_WAIT0()   asm volatile("cp.async.wait_group 0;" ::: "memory")

#define LDSM4(r, addr) \
    asm volatile("ldmatrix.sync.aligned.m8n8.x4.shared.b16 {%0,%1,%2,%3}, [%4];" \
        : "=r"((r)[0]), "=r"((r)[1]), "=r"((r)[2]), "=r"((r)[3]) : "r"(addr))

#define MMA_BF16(d, a, b) \
    asm volatile("mma.sync.aligned.m16n8k16.row.col.f32.bf16.bf16.f32 " \
        "{%0,%1,%2,%3}, {%4,%5,%6,%7}, {%8,%9}, {%0,%1,%2,%3};" \
        : "+f"((d)[0]), "+f"((d)[1]), "+f"((d)[2]), "+f"((d)[3]) \
        : "r"((a)[0]), "r"((a)[1]), "r"((a)[2]), "r"((a)[3]), "r"((b)[0]), "r"((b)[1]))

// ======================= scratch =======================
__device__ float g_x   [SEQ_L * D_MODEL];
__device__ float g_xn  [SEQ_L * D_MODEL];
__device__ float g_xr  [SEQ_L * 2 * D_INNER];
__device__ float g_xp  [SEQ_L * D_INNER];
__device__ float g_xdbl[SEQ_L * 96];
__device__ float g_dt  [SEQ_L * D_INNER];
__device__ float g_y   [SEQ_L * D_INNER];

__device__ __nv_bfloat16 g_ah[SEQ_L * D_INNER], g_al[SEQ_L * D_INNER];
__device__ __nv_bfloat16 g_bh[2 * D_INNER * D_MODEL], g_bl[2 * D_INNER * D_MODEL];
__device__ __nv_bfloat16 g_eh[(size_t)VOCAB * D_MODEL], g_el[(size_t)VOCAB * D_MODEL];

// ======================= elementwise kernels =======================
__global__ void embed_kernel(const int* __restrict__ ids, const float* __restrict__ emb,
                             float* __restrict__ x)
{
    int t = blockIdx.x;
    int id = ids[t];
    const float4* e = (const float4*)(emb + (size_t)id * D_MODEL);
    ((float4*)(x + (size_t)t * D_MODEL))[threadIdx.x] = e[threadIdx.x];
}

__global__ void rmsnorm_kernel(const float* __restrict__ x, const float* __restrict__ w,
                               float* __restrict__ out)
{
    __shared__ float red[8];
    int t = blockIdx.x;
    float4 v = ((const float4*)(x + (size_t)t * D_MODEL))[threadIdx.x];
    float s = v.x*v.x + v.y*v.y + v.z*v.z + v.w*v.w;
    #pragma unroll
    for (int off = 16; off; off >>= 1) s += __shfl_xor_sync(0xffffffffu, s, off);
    if ((threadIdx.x & 31) == 0) red[threadIdx.x >> 5] = s;
    __syncthreads();
    float tot = red[0]+red[1]+red[2]+red[3]+red[4]+red[5]+red[6]+red[7];
    float scale = rsqrtf(tot * (1.0f / (float)D_MODEL) + 1e-5f);
    float4 wv = ((const float4*)w)[threadIdx.x];
    float4 o;
    o.x = v.x * scale * wv.x; o.y = v.y * scale * wv.y;
    o.z = v.z * scale * wv.z; o.w = v.w * scale * wv.w;
    ((float4*)(out + (size_t)t * D_MODEL))[threadIdx.x] = o;
}

// fp32 -> (hi, lo) bf16 split.  src row stride ld4 float4s, row length K4 float4s, packed output.
__global__ void split_kernel(const float* __restrict__ src, int ld4, int K4,
                             __nv_bfloat16* __restrict__ h, __nv_bfloat16* __restrict__ l, int n4)
{
    int i = blockIdx.x * 256 + threadIdx.x;
    if (i >= n4) return;
    int r = i / K4;
    int c = i - r * K4;
    const float4 v = *(const float4*)(src + (size_t)r * ld4 * 4 + (size_t)c * 4);
    float f[4] = { v.x, v.y, v.z, v.w };
    __nv_bfloat162 hh[2], ll[2];
    #pragma unroll
    for (int q = 0; q < 2; q++) {
        __nv_bfloat16 h0 = __float2bfloat16(f[2*q]);
        __nv_bfloat16 h1 = __float2bfloat16(f[2*q+1]);
        hh[q].x = h0; hh[q].y = h1;
        ll[q].x = __float2bfloat16(f[2*q]   - __bfloat162float(h0));
        ll[q].y = __float2bfloat16(f[2*q+1] - __bfloat162float(h1));
    }
    ((__nv_bfloat162*)h)[2*i]   = hh[0];
    ((__nv_bfloat162*)h)[2*i+1] = hh[1];
    ((__nv_bfloat162*)l)[2*i]   = ll[0];
    ((__nv_bfloat162*)l)[2*i+1] = ll[1];
}

__global__ void conv_silu_kernel(const float* __restrict__ xr, const float* __restrict__ w,
                                 const float* __restrict__ b, float* __restrict__ xp)
{
    int idx = blockIdx.x * 256 + threadIdx.x;
    int c = idx & (D_INNER - 1);
    int t = idx >> 11;
    float w0 = w[c*4+0], w1 = w[c*4+1], w2 = w[c*4+2], w3 = w[c*4+3];
    float acc = b[c];
    const float* col = xr + c;
    const int stride = 2 * D_INNER;
    if (t >= 3) acc += w0 * col[(size_t)(t-3) * stride];
    if (t >= 2) acc += w1 * col[(size_t)(t-2) * stride];
    if (t >= 1) acc += w2 * col[(size_t)(t-1) * stride];
    acc += w3 * col[(size_t)t * stride];
    xp[idx] = acc / (1.f + __expf(-acc));
}

// ======================= selective scan =======================
__global__ __launch_bounds__(128)
void scan_kernel(const float* __restrict__ delta, const float* __restrict__ u,
                 const float* __restrict__ xdbl,  const float* __restrict__ A_log,
                 const float* __restrict__ Dp,    const float* __restrict__ xr,
                 float* __restrict__ y)
{
    int tid = threadIdx.x;
    int n = tid & 15;
    int d = blockIdx.x * (blockDim.x >> 4) + (tid >> 4);
    float A  = -__expf(A_log[d * D_STATE + n]);
    float Dv = Dp[d];
    float h = 0.f;
    const float* dptr = delta + d;
    const float* uptr = u + d;
    const float* bptr = xdbl + 64 + n;
    const float* cptr = xdbl + 80 + n;
    const float* rptr = xr + D_INNER + d;
    #pragma unroll 4
    for (int t = 0; t < SEQ_L; t++) {
        float dt = dptr[(size_t)t * D_INNER];
        float uu = uptr[(size_t)t * D_INNER];
        float bb = bptr[(size_t)t * 96];
        float cc = cptr[(size_t)t * 96];
        float dA = __expf(dt * A);
        h = dA * h + (dt * uu) * bb;
        float p = h * cc;
        p += __shfl_xor_sync(0xffffffffu, p, 8);
        p += __shfl_xor_sync(0xffffffffu, p, 4);
        p += __shfl_xor_sync(0xffffffffu, p, 2);
        p += __shfl_xor_sync(0xffffffffu, p, 1);
        if (n == 0) {
            float r = rptr[(size_t)t * (2 * D_INNER)];
            float g = r / (1.f + __expf(-r));
            y[(size_t)t * D_INNER + d] = (p + uu * Dv) * g;
        }
    }
}

// ======================= HMMA 3-term bf16 GEMM =======================
// C[M, Nrows] = A[M,K] * B[Nrows,K]^T,  A = Ah+Al, B = Bh+Bl (bf16 splits), fp32 acc.
// CTA tile 128x128, K-chunk 64 bf16 (128B rows, SW128). 8 warps in 2(M)x4(N), warp 64x32.
// EPI: 0 = store, 1 = C += acc, 2 = softplus(acc + X[n])
#define SA_H 0
#define SA_L 16384
#define SB_H 32768
#define SB_L 49152
#define S_TOT 65536

template<int EPI>
__global__ __launch_bounds__(256, 2)
void gemm_mma(const __nv_bfloat16* __restrict__ Ah, const __nv_bfloat16* __restrict__ Al,
              const __nv_bfloat16* __restrict__ Bh, const __nv_bfloat16* __restrict__ Bl,
              float* __restrict__ C, int ldc, const float* __restrict__ X,
              int Nrows, int K)
{
    extern __shared__ char smem[];
    const uint32_t sb = smem_u32(smem);
    const int tid  = threadIdx.x;
    const int lane = tid & 31, wid = tid >> 5;
    const int wm = wid & 1, wn = wid >> 1;              // 2 x 4 warp grid
    const int bm = blockIdx.y * 128, bn = blockIdx.x * 128;

    float d[4][4][4];
    #pragma unroll
    for (int i = 0; i < 4; i++)
        #pragma unroll
        for (int j = 0; j < 4; j++)
            #pragma unroll
            for (int q = 0; q < 4; q++) d[i][j][q] = 0.f;

    const int nch = K >> 6;
    const size_t rowb = (size_t)K * 2;                  // bytes per row

    for (int c = 0; c < nch; c++) {
        const size_t gkb = (size_t)c * 128;             // byte offset of chunk in a row
        // ---- load chunk: 4 tiles of 128 rows x 128B via cp.async ----
        #pragma unroll
        for (int it = 0; it < 4; it++) {
            int i = tid + it * 256;                     // 0..1023
            int r = i >> 3, ch = i & 7;
            uint32_t so = SWZ128((uint32_t)(r * 128 + ch * 16));
            const char* ga = (const char*)Ah + (size_t)(bm + r) * rowb + gkb + ch * 16;
            const char* gl = (const char*)Al + (size_t)(bm + r) * rowb + gkb + ch * 16;
            CP_ASYNC16(sb + SA_H + so, ga);
            CP_ASYNC16(sb + SA_L + so, gl);
            int valid = (bn + r) < Nrows ? 16 : 0;
            size_t boff = valid ? ((size_t)(bn + r) * rowb + gkb + ch * 16) : 0;
            CP_ASYNC16_Z(sb + SB_H + so, (const char*)Bh + boff, valid);
            CP_ASYNC16_Z(sb + SB_L + so, (const char*)Bl + boff, valid);
        }
        CP_COMMIT();
        CP_WAIT0();
        __syncthreads();

        // ---- compute: 4 k16 steps ----
        const int mat = lane >> 3, r8 = lane & 7;
        #pragma unroll
        for (int kk = 0; kk < 4; kk++) {
            uint32_t ah_[4][4], al_[4][4];
            #pragma unroll
            for (int mf = 0; mf < 4; mf++) {
                int mrow = wm * 64 + mf * 16 + r8 + (mat & 1) * 8;
                int kb   = kk * 32 + (mat >> 1) * 16;
                uint32_t so = SWZ128((uint32_t)(mrow * 128 + kb));
                LDSM4(ah_[mf], sb + SA_H + so);
                LDSM4(al_[mf], sb + SA_L + so);
            }
            #pragma unroll
            for (int p = 0; p < 2; p++) {
                uint32_t bh_[4], bl_[4];
                int nrow = wn * 32 + p * 16 + r8 + (mat >> 1) * 8;
                int kb   = kk * 32 + (mat & 1) * 16;
                uint32_t so = SWZ128((uint32_t)(nrow * 128 + kb));
                LDSM4(bh_, sb + SB_H + so);
                LDSM4(bl_, sb + SB_L + so);
                #pragma unroll
                for (int mf = 0; mf < 4; mf++) {
                    #pragma unroll
                    for (int q = 0; q < 2; q++) {
                        float* dd = d[mf][p * 2 + q];
                        MMA_BF16(dd, ah_[mf], (&bh_[q * 2]));
                        MMA_BF16(dd, ah_[mf], (&bl_[q * 2]));
                        MMA_BF16(dd, al_[mf], (&bh_[q * 2]));
                    }
                }
            }
        }
        __syncthreads();
    }

    // ---- epilogue ----
    const bool interior = (bn + 128) <= Nrows;
    const int g = lane >> 2, tg = (lane & 3) * 2;
    #pragma unroll
    for (int mf = 0; mf < 4; mf++) {
        int row0 = bm + wm * 64 + mf * 16 + g;
        #pragma unroll
        for (int hh = 0; hh < 2; hh++) {
            float* rp = C + (size_t)(row0 + hh * 8) * ldc;
            #pragma unroll
            for (int nf = 0; nf < 4; nf++) {
                int col = bn + wn * 32 + nf * 8 + tg;
                float v0 = d[mf][nf][hh * 2];
                float v1 = d[mf][nf][hh * 2 + 1];
                if (EPI == 1) { v0 += rp[col]; v1 += rp[col + 1]; }
                if (EPI == 2) {
                    float z0 = v0 + X[col], z1 = v1 + X[col + 1];
                    v0 = (z0 > 20.f) ? z0 : log1pf(__expf(z0));
                    v1 = (z1 > 20.f) ? z1 : log1pf(__expf(z1));
                }
                if (interior) {
                    *(float2*)(rp + col) = make_float2(v0, v1);
                } else {
                    if (col < Nrows)     rp[col]     = v0;
                    if (col + 1 < Nrows) rp[col + 1] = v1;
                }
            }
        }
    }
}

// ======================= driver =======================
static inline void do_split(const float* src, int ld4, int K4, __nv_bfloat16* h,
                            __nv_bfloat16* l, int n4)
{
    split_kernel<<<(n4 + 255) / 256, 256>>>(src, ld4, K4, h, l, n4);
}

extern "C" void kernel_launch(void* const* d_in, const int* in_sizes, int n_in,
                              void* d_out, int out_size)
{
    const int*   ids    = (const int*)  d_in[0];
    const float* emb    = (const float*)d_in[1];
    const float* inpw   = (const float*)d_in[2];
    const float* convw  = (const float*)d_in[3];
    const float* convb  = (const float*)d_in[4];
    const float* xprojw = (const float*)d_in[5];
    const float* dtw    = (const float*)d_in[6];
    const float* dtb    = (const float*)d_in[7];
    const float* alog   = (const float*)d_in[8];
    const float* dpar   = (const float*)d_in[9];
    const float* outw   = (const float*)d_in[10];
    const float* normw  = (const float*)d_in[11];
    const float* normf  = (const float*)d_in[12];
    float* logits = (float*)d_out;

    cudaFuncSetAttribute(gemm_mma<0>, cudaFuncAttributeMaxDynamicSharedMemorySize, S_TOT);
    cudaFuncSetAttribute(gemm_mma<1>, cudaFuncAttributeMaxDynamicSharedMemorySize, S_TOT);
    cudaFuncSetAttribute(gemm_mma<2>, cudaFuncAttributeMaxDynamicSharedMemorySize, S_TOT);

    float *x, *xn, *xr, *xp, *xdbl, *dt, *y;
    __nv_bfloat16 *ah, *al, *bh, *bl, *eh, *el;
    cudaGetSymbolAddress((void**)&x,    g_x);
    cudaGetSymbolAddress((void**)&xn,   g_xn);
    cudaGetSymbolAddress((void**)&xr,   g_xr);
    cudaGetSymbolAddress((void**)&xp,   g_xp);
    cudaGetSymbolAddress((void**)&xdbl, g_xdbl);
    cudaGetSymbolAddress((void**)&dt,   g_dt);
    cudaGetSymbolAddress((void**)&y,    g_y);
    cudaGetSymbolAddress((void**)&ah,   g_ah);
    cudaGetSymbolAddress((void**)&al,   g_al);
    cudaGetSymbolAddress((void**)&bh,   g_bh);
    cudaGetSymbolAddress((void**)&bl,   g_bl);
    cudaGetSymbolAddress((void**)&eh,   g_eh);
    cudaGetSymbolAddress((void**)&el,   g_el);

    embed_kernel<<<SEQ_L, 256>>>(ids, emb, x);

    // split embedding once (B operand of logits GEMM)
    do_split(emb, D_MODEL / 4, D_MODEL / 4, eh, el, VOCAB * (D_MODEL / 4));

    for (int i = 0; i < N_LAYER; i++) {
        const float* w_in   = inpw   + (size_t)i * (2 * D_INNER) * D_MODEL;
        const float* w_conv = convw  + (size_t)i * D_INNER * 4;
        const float* b_conv = convb  + (size_t)i * D_INNER;
        const float* w_xprj = xprojw + (size_t)i * 96 * D_INNER;
        const float* w_dt   = dtw    + (size_t)i * D_INNER * DT_RANK;
        const float* b_dt   = dtb    + (size_t)i * D_INNER;
        const float* a_log  = alog   + (size_t)i * D_INNER * D_STATE;
        const float* d_prm  = dpar   + (size_t)i * D_INNER;
        const float* w_out  = outw   + (size_t)i * D_MODEL * D_INNER;
        const float* w_nrm  = normw  + (size_t)i * D_MODEL;

        rmsnorm_kernel<<<SEQ_L, 256>>>(x, w_nrm, xn);

        // in_proj: M=2048, N=4096, K=1024
        do_split(xn,   256, 256, ah, al, SEQ_L * 256);
        do_split(w_in, 256, 256, bh, bl, (2 * D_INNER) * 256);
        gemm_mma<0><<<dim3((2 * D_INNER) / 128, SEQ_L / 128), 256, S_TOT>>>(
            ah, al, bh, bl, xr, 2 * D_INNER, nullptr, 2 * D_INNER, D_MODEL);

        conv_silu_kernel<<<(SEQ_L * D_INNER) / 256, 256>>>(xr, w_conv, b_conv, xp);

        // x_proj: M=2048, N=96, K=2048
        do_split(xp,     512, 512, ah, al, SEQ_L * 512);
        do_split(w_xprj, 512, 512, bh, bl, 96 * 512);
        gemm_mma<0><<<dim3(1, SEQ_L / 128), 256, S_TOT>>>(
            ah, al, bh, bl, xdbl, 96, nullptr, 96, D_INNER);

        // dt_proj + softplus: M=2048, N=2048, K=64  (A = xdbl[:, :64] packed)
        do_split(xdbl, 24, 16, ah, al, SEQ_L * 16);
        do_split(w_dt, 16, 16, bh, bl, D_INNER * 16);
        gemm_mma<2><<<dim3(D_INNER / 128, SEQ_L / 128), 256, S_TOT>>>(
            ah, al, bh, bl, dt, D_INNER, b_dt, D_INNER, DT_RANK);

        scan_kernel<<<D_INNER / 8, 128>>>(dt, xp, xdbl, a_log, d_prm, xr, y);

        // out_proj (+residual): M=2048, N=1024, K=2048
        do_split(y,     512, 512, ah, al, SEQ_L * 512);
        do_split(w_out, 512, 512, bh, bl, D_MODEL * 512);
        gemm_mma<1><<<dim3(D_MODEL / 128, SEQ_L / 128), 256, S_TOT>>>(
            ah, al, bh, bl, x, D_MODEL, nullptr, D_MODEL, D_INNER);
    }

    rmsnorm_kernel<<<SEQ_L, 256>>>(x, normf, xn);

    // logits: M=2048, N=50264, K=1024
    do_split(xn, 256, 256, ah, al, SEQ_L * 256);
    gemm_mma<0><<<dim3((VOCAB + 127) / 128, SEQ_L / 128), 256, S_TOT>>>(
        ah, al, eh, el, logits, VOCAB, nullptr, VOCAB, D_MODEL);
}

// round 8
// speedup vs baseline: 2.3210x; 1.3581x over previous
#include <cuda_runtime.h>
#include <cuda_fp16.h>
#include <cstdint>

#define D_MODEL 1024
#define N_LAYER 2
#define VOCAB   50264
#define D_STATE 16
#define D_INNER 2048
#define DT_RANK 64
#define SEQ_L   2048

// ======================= helpers =======================
__device__ __forceinline__ uint32_t smem_u32(const void* p) {
    uint32_t a;
    asm("{ .reg .u64 t; cvta.to.shared.u64 t, %1; cvt.u32.u64 %0, t; }" : "=r"(a) : "l"(p));
    return a;
}
#define SWZ128(b) ((b) ^ (((b) >> 3) & 0x70))

#define CP_ASYNC16(saddr, gaddr) \
    asm volatile("cp.async.cg.shared.global [%0], [%1], 16;" :: "r"(saddr), "l"(gaddr) : "memory")
#define CP_ASYNC16_Z(saddr, gaddr, sz) \
    asm volatile("cp.async.cg.shared.global [%0], [%1], 16, %2;" :: "r"(saddr), "l"(gaddr), "r"(sz) : "memory")
#define CP_COMMIT()  asm volatile("cp.async.commit_group;" ::: "memory")
#define CP_WAIT0()   asm volatile("cp.async.wait_group 0;" ::: "memory")
#define CP_WAIT1()   asm volatile("cp.async.wait_group 1;" ::: "memory")

#define LDSM4(r, addr) \
    asm volatile("ldmatrix.sync.aligned.m8n8.x4.shared.b16 {%0,%1,%2,%3}, [%4];" \
        : "=r"((r)[0]), "=r"((r)[1]), "=r"((r)[2]), "=r"((r)[3]) : "r"(addr))

#define MMA_FP16(d, a, b) \
    asm volatile("mma.sync.aligned.m16n8k16.row.col.f32.f16.f16.f32 " \
        "{%0,%1,%2,%3}, {%4,%5,%6,%7}, {%8,%9}, {%0,%1,%2,%3};" \
        : "+f"((d)[0]), "+f"((d)[1]), "+f"((d)[2]), "+f"((d)[3]) \
        : "r"((a)[0]), "r"((a)[1]), "r"((a)[2]), "r"((a)[3]), "r"((b)[0]), "r"((b)[1]))

// ======================= scratch =======================
__device__ float g_x   [SEQ_L * D_MODEL];
__device__ float g_xn  [SEQ_L * D_MODEL];
__device__ float g_xr  [SEQ_L * 2 * D_INNER];
__device__ float g_xp  [SEQ_L * D_INNER];
__device__ float g_xdbl[SEQ_L * 96];
__device__ float g_dt  [SEQ_L * D_INNER];
__device__ float g_y   [SEQ_L * D_INNER];

__device__ __half g_a[SEQ_L * D_INNER];                 // A operand (max 2048x2048)
__device__ __half g_b[2 * D_INNER * D_MODEL];           // B operand (max 4096x1024)
__device__ __half g_e[(size_t)VOCAB * D_MODEL];         // fp16 embedding (logits B)

// ======================= elementwise kernels =======================
__global__ void embed_kernel(const int* __restrict__ ids, const float* __restrict__ emb,
                             float* __restrict__ x)
{
    int t = blockIdx.x;
    int id = ids[t];
    const float4* e = (const float4*)(emb + (size_t)id * D_MODEL);
    ((float4*)(x + (size_t)t * D_MODEL))[threadIdx.x] = e[threadIdx.x];
}

__global__ void rmsnorm_kernel(const float* __restrict__ x, const float* __restrict__ w,
                               float* __restrict__ out)
{
    __shared__ float red[8];
    int t = blockIdx.x;
    float4 v = ((const float4*)(x + (size_t)t * D_MODEL))[threadIdx.x];
    float s = v.x*v.x + v.y*v.y + v.z*v.z + v.w*v.w;
    #pragma unroll
    for (int off = 16; off; off >>= 1) s += __shfl_xor_sync(0xffffffffu, s, off);
    if ((threadIdx.x & 31) == 0) red[threadIdx.x >> 5] = s;
    __syncthreads();
    float tot = red[0]+red[1]+red[2]+red[3]+red[4]+red[5]+red[6]+red[7];
    float scale = rsqrtf(tot * (1.0f / (float)D_MODEL) + 1e-5f);
    float4 wv = ((const float4*)w)[threadIdx.x];
    float4 o;
    o.x = v.x * scale * wv.x; o.y = v.y * scale * wv.y;
    o.z = v.z * scale * wv.z; o.w = v.w * scale * wv.w;
    ((float4*)(out + (size_t)t * D_MODEL))[threadIdx.x] = o;
}

// fp32 -> fp16 convert. src row stride ld4 float4s, row length K4 float4s, packed output.
__global__ void cvt_kernel(const float* __restrict__ src, int ld4, int K4,
                           __half* __restrict__ out, int n4)
{
    int i = blockIdx.x * 256 + threadIdx.x;
    if (i >= n4) return;
    int r = i / K4;
    int c = i - r * K4;
    const float4 v = *(const float4*)(src + (size_t)r * ld4 * 4 + (size_t)c * 4);
    __half2* o = (__half2*)out;
    o[2*i]   = __floats2half2_rn(v.x, v.y);
    o[2*i+1] = __floats2half2_rn(v.z, v.w);
}

__global__ void conv_silu_kernel(const float* __restrict__ xr, const float* __restrict__ w,
                                 const float* __restrict__ b, float* __restrict__ xp)
{
    int idx = blockIdx.x * 256 + threadIdx.x;
    int c = idx & (D_INNER - 1);
    int t = idx >> 11;
    float w0 = w[c*4+0], w1 = w[c*4+1], w2 = w[c*4+2], w3 = w[c*4+3];
    float acc = b[c];
    const float* col = xr + c;
    const int stride = 2 * D_INNER;
    if (t >= 3) acc += w0 * col[(size_t)(t-3) * stride];
    if (t >= 2) acc += w1 * col[(size_t)(t-2) * stride];
    if (t >= 1) acc += w2 * col[(size_t)(t-1) * stride];
    acc += w3 * col[(size_t)t * stride];
    xp[idx] = acc / (1.f + __expf(-acc));
}

// ======================= selective scan =======================
__global__ __launch_bounds__(128)
void scan_kernel(const float* __restrict__ delta, const float* __restrict__ u,
                 const float* __restrict__ xdbl,  const float* __restrict__ A_log,
                 const float* __restrict__ Dp,    const float* __restrict__ xr,
                 float* __restrict__ y)
{
    int tid = threadIdx.x;
    int n = tid & 15;
    int d = blockIdx.x * (blockDim.x >> 4) + (tid >> 4);
    float A  = -__expf(A_log[d * D_STATE + n]);
    float Dv = Dp[d];
    float h = 0.f;
    const float* dptr = delta + d;
    const float* uptr = u + d;
    const float* bptr = xdbl + 64 + n;
    const float* cptr = xdbl + 80 + n;
    const float* rptr = xr + D_INNER + d;
    #pragma unroll 4
    for (int t = 0; t < SEQ_L; t++) {
        float dt = dptr[(size_t)t * D_INNER];
        float uu = uptr[(size_t)t * D_INNER];
        float bb = bptr[(size_t)t * 96];
        float cc = cptr[(size_t)t * 96];
        float dA = __expf(dt * A);
        h = dA * h + (dt * uu) * bb;
        float p = h * cc;
        p += __shfl_xor_sync(0xffffffffu, p, 8);
        p += __shfl_xor_sync(0xffffffffu, p, 4);
        p += __shfl_xor_sync(0xffffffffu, p, 2);
        p += __shfl_xor_sync(0xffffffffu, p, 1);
        if (n == 0) {
            float r = rptr[(size_t)t * (2 * D_INNER)];
            float g = r / (1.f + __expf(-r));
            y[(size_t)t * D_INNER + d] = (p + uu * Dv) * g;
        }
    }
}

// ======================= HMMA fp16 GEMM, 2-stage cp.async pipeline ============
// C[M, Nrows] = A[M,K] * B[Nrows,K]^T, fp16 operands, fp32 acc.
// CTA tile 128x128, K-chunk 64 (128B rows, SW128). 8 warps 2(M)x4(N), warp 64x32.
// EPI: 0 = store, 1 = C += acc, 2 = softplus(acc + X[n])
#define S_STAGE 16384
#define SB_OFF  32768
#define S_TOT   65536

template<int EPI>
__global__ __launch_bounds__(256, 2)
void gemm_mma(const __half* __restrict__ A, const __half* __restrict__ B,
              float* __restrict__ C, int ldc, const float* __restrict__ X,
              int Nrows, int K)
{
    extern __shared__ char smem[];
    const uint32_t sb = smem_u32(smem);
    const int tid  = threadIdx.x;
    const int lane = tid & 31, wid = tid >> 5;
    const int wm = wid & 1, wn = wid >> 1;
    const int bm = blockIdx.y * 128, bn = blockIdx.x * 128;
    const int nch = K >> 6;
    const size_t rowb = (size_t)K * 2;

    float d[4][4][4];
    #pragma unroll
    for (int i = 0; i < 4; i++)
        #pragma unroll
        for (int j = 0; j < 4; j++)
            #pragma unroll
            for (int q = 0; q < 4; q++) d[i][j][q] = 0.f;

    // per-thread load coords: 4 rows x 1 chunk-of-16B each for A and B
    const int lr = tid >> 3, lch = tid & 7;   // base row 0..31 (x4), chunk 0..7

    // ---- prologue: load chunk 0 into stage 0 ----
    {
        #pragma unroll
        for (int it = 0; it < 4; it++) {
            int r = lr + it * 32;
            uint32_t so = SWZ128((uint32_t)(r * 128 + lch * 16));
            CP_ASYNC16(sb + so, (const char*)A + (size_t)(bm + r) * rowb + lch * 16);
            int valid = (bn + r) < Nrows ? 16 : 0;
            size_t boff = valid ? ((size_t)(bn + r) * rowb + lch * 16) : 0;
            CP_ASYNC16_Z(sb + SB_OFF + so, (const char*)B + boff, valid);
        }
        CP_COMMIT();
    }

    for (int c = 0; c < nch; c++) {
        const int s = c & 1;
        if (c + 1 < nch) {
            const size_t gkb = (size_t)(c + 1) * 128;
            const uint32_t st = (uint32_t)(1 - s) * S_STAGE;
            #pragma unroll
            for (int it = 0; it < 4; it++) {
                int r = lr + it * 32;
                uint32_t so = SWZ128((uint32_t)(r * 128 + lch * 16));
                CP_ASYNC16(sb + st + so, (const char*)A + (size_t)(bm + r) * rowb + gkb + lch * 16);
                int valid = (bn + r) < Nrows ? 16 : 0;
                size_t boff = valid ? ((size_t)(bn + r) * rowb + gkb + lch * 16) : 0;
                CP_ASYNC16_Z(sb + SB_OFF + st + so, (const char*)B + boff, valid);
            }
            CP_COMMIT();
            CP_WAIT1();
        } else {
            CP_WAIT0();
        }
        __syncthreads();

        const uint32_t sa = sb + s * S_STAGE;
        const uint32_t sbb = sb + SB_OFF + s * S_STAGE;
        const int mat = lane >> 3, r8 = lane & 7;
        #pragma unroll
        for (int kk = 0; kk < 4; kk++) {
            uint32_t a_[4][4];
            #pragma unroll
            for (int mf = 0; mf < 4; mf++) {
                int mrow = wm * 64 + mf * 16 + r8 + (mat & 1) * 8;
                int kb   = kk * 32 + (mat >> 1) * 16;
                LDSM4(a_[mf], sa + SWZ128((uint32_t)(mrow * 128 + kb)));
            }
            #pragma unroll
            for (int p = 0; p < 2; p++) {
                uint32_t b_[4];
                int nrow = wn * 32 + p * 16 + r8 + (mat >> 1) * 8;
                int kb   = kk * 32 + (mat & 1) * 16;
                LDSM4(b_, sbb + SWZ128((uint32_t)(nrow * 128 + kb)));
                #pragma unroll
                for (int mf = 0; mf < 4; mf++) {
                    #pragma unroll
                    for (int q = 0; q < 2; q++) {
                        MMA_FP16(d[mf][p * 2 + q], a_[mf], (&b_[q * 2]));
                    }
                }
            }
        }
        __syncthreads();
    }

    // ---- epilogue ----
    const bool interior = (bn + 128) <= Nrows;
    const int g = lane >> 2, tg = (lane & 3) * 2;
    #pragma unroll
    for (int mf = 0; mf < 4; mf++) {
        int row0 = bm + wm * 64 + mf * 16 + g;
        #pragma unroll
        for (int hh = 0; hh < 2; hh++) {
            float* rp = C + (size_t)(row0 + hh * 8) * ldc;
            #pragma unroll
            for (int nf = 0; nf < 4; nf++) {
                int col = bn + wn * 32 + nf * 8 + tg;
                float v0 = d[mf][nf][hh * 2];
                float v1 = d[mf][nf][hh * 2 + 1];
                if (EPI == 1) { v0 += rp[col]; v1 += rp[col + 1]; }
                if (EPI == 2) {
                    float z0 = v0 + X[col], z1 = v1 + X[col + 1];
                    v0 = (z0 > 20.f) ? z0 : log1pf(__expf(z0));
                    v1 = (z1 > 20.f) ? z1 : log1pf(__expf(z1));
                }
                if (interior) {
                    *(float2*)(rp + col) = make_float2(v0, v1);
                } else {
                    if (col < Nrows)     rp[col]     = v0;
                    if (col + 1 < Nrows) rp[col + 1] = v1;
                }
            }
        }
    }
}

// ======================= driver =======================
static inline void do_cvt(const float* src, int ld4, int K4, __half* out, int n4)
{
    cvt_kernel<<<(n4 + 255) / 256, 256>>>(src, ld4, K4, out, n4);
}

extern "C" void kernel_launch(void* const* d_in, const int* in_sizes, int n_in,
                              void* d_out, int out_size)
{
    const int*   ids    = (const int*)  d_in[0];
    const float* emb    = (const float*)d_in[1];
    const float* inpw   = (const float*)d_in[2];
    const float* convw  = (const float*)d_in[3];
    const float* convb  = (const float*)d_in[4];
    const float* xprojw = (const float*)d_in[5];
    const float* dtw    = (const float*)d_in[6];
    const float* dtb    = (const float*)d_in[7];
    const float* alog   = (const float*)d_in[8];
    const float* dpar   = (const float*)d_in[9];
    const float* outw   = (const float*)d_in[10];
    const float* normw  = (const float*)d_in[11];
    const float* normf  = (const float*)d_in[12];
    float* logits = (float*)d_out;

    cudaFuncSetAttribute(gemm_mma<0>, cudaFuncAttributeMaxDynamicSharedMemorySize, S_TOT);
    cudaFuncSetAttribute(gemm_mma<1>, cudaFuncAttributeMaxDynamicSharedMemorySize, S_TOT);
    cudaFuncSetAttribute(gemm_mma<2>, cudaFuncAttributeMaxDynamicSharedMemorySize, S_TOT);

    float *x, *xn, *xr, *xp, *xdbl, *dt, *y;
    __half *a, *b, *e;
    cudaGetSymbolAddress((void**)&x,    g_x);
    cudaGetSymbolAddress((void**)&xn,   g_xn);
    cudaGetSymbolAddress((void**)&xr,   g_xr);
    cudaGetSymbolAddress((void**)&xp,   g_xp);
    cudaGetSymbolAddress((void**)&xdbl, g_xdbl);
    cudaGetSymbolAddress((void**)&dt,   g_dt);
    cudaGetSymbolAddress((void**)&y,    g_y);
    cudaGetSymbolAddress((void**)&a,    g_a);
    cudaGetSymbolAddress((void**)&b,    g_b);
    cudaGetSymbolAddress((void**)&e,    g_e);

    embed_kernel<<<SEQ_L, 256>>>(ids, emb, x);

    // fp16 embedding (logits B operand), once
    do_cvt(emb, D_MODEL / 4, D_MODEL / 4, e, VOCAB * (D_MODEL / 4));

    for (int i = 0; i < N_LAYER; i++) {
        const float* w_in   = inpw   + (size_t)i * (2 * D_INNER) * D_MODEL;
        const float* w_conv = convw  + (size_t)i * D_INNER * 4;
        const float* b_conv = convb  + (size_t)i * D_INNER;
        const float* w_xprj = xprojw + (size_t)i * 96 * D_INNER;
        const float* w_dt   = dtw    + (size_t)i * D_INNER * DT_RANK;
        const float* b_dt   = dtb    + (size_t)i * D_INNER;
        const float* a_log  = alog   + (size_t)i * D_INNER * D_STATE;
        const float* d_prm  = dpar   + (size_t)i * D_INNER;
        const float* w_out  = outw   + (size_t)i * D_MODEL * D_INNER;
        const float* w_nrm  = normw  + (size_t)i * D_MODEL;

        rmsnorm_kernel<<<SEQ_L, 256>>>(x, w_nrm, xn);

        // in_proj: M=2048, N=4096, K=1024
        do_cvt(xn,   256, 256, a, SEQ_L * 256);
        do_cvt(w_in, 256, 256, b, (2 * D_INNER) * 256);
        gemm_mma<0><<<dim3((2 * D_INNER) / 128, SEQ_L / 128), 256, S_TOT>>>(
            a, b, xr, 2 * D_INNER, nullptr, 2 * D_INNER, D_MODEL);

        conv_silu_kernel<<<(SEQ_L * D_INNER) / 256, 256>>>(xr, w_conv, b_conv, xp);

        // x_proj: M=2048, N=96, K=2048
        do_cvt(xp,     512, 512, a, SEQ_L * 512);
        do_cvt(w_xprj, 512, 512, b, 96 * 512);
        gemm_mma<0><<<dim3(1, SEQ_L / 128), 256, S_TOT>>>(
            a, b, xdbl, 96, nullptr, 96, D_INNER);

        // dt_proj + softplus: M=2048, N=2048, K=64  (A = xdbl[:, :64] packed)
        do_cvt(xdbl, 24, 16, a, SEQ_L * 16);
        do_cvt(w_dt, 16, 16, b, D_INNER * 16);
        gemm_mma<2><<<dim3(D_INNER / 128, SEQ_L / 128), 256, S_TOT>>>(
            a, b, dt, D_INNER, b_dt, D_INNER, DT_RANK);

        scan_kernel<<<D_INNER / 8, 128>>>(dt, xp, xdbl, a_log, d_prm, xr, y);

        // out_proj (+residual): M=2048, N=1024, K=2048
        do_cvt(y,     512, 512, a, SEQ_L * 512);
        do_cvt(w_out, 512, 512, b, D_MODEL * 512);
        gemm_mma<1><<<dim3(D_MODEL / 128, SEQ_L / 128), 256, S_TOT>>>(
            a, b, x, D_MODEL, nullptr, D_MODEL, D_INNER);
    }

    rmsnorm_kernel<<<SEQ_L, 256>>>(x, normf, xn);

    // logits: M=2048, N=50264, K=1024
    do_cvt(xn, 256, 256, a, SEQ_L * 256);
    gemm_mma<0><<<dim3((VOCAB + 127) / 128, SEQ_L / 128), 256, S_TOT>>>(
        a, e, logits, VOCAB, nullptr, VOCAB, D_MODEL);
}